// round 1
// baseline (speedup 1.0000x reference)
#include <cuda_runtime.h>

// RMAC max-pooling, x: (64, 37, 37, 512) f32 NHWC -> out: (64, 14, 512) f32.
// 14 static regions = products of 6 axis-intervals; intervals = unions of 7
// atomic segments with boundaries {0,9,13,18,19,24,27,37}.
//
// K1: per (h-segment, batch) block, stream the input once, keep 7 per-w-segment
//     running maxes in registers (w-loop fully unrolled so accumulator choice is
//     compile-time), combine into 6 w-interval maxes, store to g_M.
// K2: per (region, batch) block, max over the h-segments belonging to the
//     region's y-interval at the region's x-interval row. Reads g_M (L2-hot).

#define NEG_INF __int_as_float(0xff800000)

__device__ float g_M[64 * 7 * 6 * 512];  // 5.5 MB scratch (alloc-free rule: device global)

__constant__ int c_segStart[7] = {0, 9, 13, 18, 19, 24, 27};
__constant__ int c_segEnd[7]   = {9, 13, 18, 19, 24, 27, 37};

// region r -> (y-interval, x-interval); intervals: 0:[0,37) 1:[0,24) 2:[13,37)
//                                                  3:[0,18) 4:[9,27) 5:[19,37)
__constant__ unsigned char c_regY[14]  = {0, 1, 1, 2, 2, 3, 3, 3, 4, 4, 4, 5, 5, 5};
__constant__ unsigned char c_regX[14]  = {0, 1, 2, 1, 2, 3, 4, 5, 3, 4, 5, 3, 4, 5};
// interval -> bitmask of atomic segments it covers
__constant__ unsigned char c_imask[6]  = {0x7F, 0x1F, 0x7C, 0x07, 0x3E, 0x70};

__device__ __forceinline__ float4 fmax4(float4 a, float4 b) {
    return make_float4(fmaxf(a.x, b.x), fmaxf(a.y, b.y),
                       fmaxf(a.z, b.z), fmaxf(a.w, b.w));
}

__global__ __launch_bounds__(128) void rmac_k1(const float* __restrict__ x) {
    const int s  = blockIdx.x;   // h-segment 0..6
    const int b  = blockIdx.y;   // batch 0..63
    const int c4 = threadIdx.x;  // channel group: 4 floats each, 128*4 = 512

    const float4* __restrict__ x4 = (const float4*)x;

    float4 ninf = make_float4(NEG_INF, NEG_INF, NEG_INF, NEG_INF);
    float4 a0 = ninf, a1 = ninf, a2 = ninf, a3 = ninf, a4 = ninf, a5 = ninf, a6 = ninf;

    const int h0 = c_segStart[s];
    const int h1 = c_segEnd[s];

    for (int h = h0; h < h1; ++h) {
        // float4 row base: ((b*37 + h)*37 + w)*128 + c4
        size_t rb = ((size_t)(b * 37 + h) * 37) * 128 + c4;
#pragma unroll
        for (int w = 0; w < 37; ++w) {
            float4 v = x4[rb + (size_t)w * 128];
            if      (w <  9) a0 = fmax4(a0, v);
            else if (w < 13) a1 = fmax4(a1, v);
            else if (w < 18) a2 = fmax4(a2, v);
            else if (w < 19) a3 = fmax4(a3, v);
            else if (w < 24) a4 = fmax4(a4, v);
            else if (w < 27) a5 = fmax4(a5, v);
            else             a6 = fmax4(a6, v);
        }
    }

    // Combine 7 w-segments -> 6 w-interval maxes.
    float4 I3 = fmax4(fmax4(a0, a1), a2);          // [0,18)  = s0..s2
    float4 I1 = fmax4(fmax4(I3, a3), a4);          // [0,24)  = s0..s4
    float4 I5 = fmax4(fmax4(a4, a5), a6);          // [19,37) = s4..s6
    float4 I0 = fmax4(I1, fmax4(a5, a6));          // [0,37)  = s0..s6
    float4 I2 = fmax4(fmax4(a2, a3), I5);          // [13,37) = s2..s6
    float4 I4 = fmax4(fmax4(a1, a2), fmax4(a3, fmax4(a4, a5)));  // [9,27) = s1..s5

    float4* M4 = (float4*)g_M;
    size_t ob = ((size_t)(b * 7 + s) * 6) * 128 + c4;
    M4[ob + 0 * 128] = I0;
    M4[ob + 1 * 128] = I1;
    M4[ob + 2 * 128] = I2;
    M4[ob + 3 * 128] = I3;
    M4[ob + 4 * 128] = I4;
    M4[ob + 5 * 128] = I5;
}

__global__ __launch_bounds__(128) void rmac_k2(float* __restrict__ out) {
    const int r  = blockIdx.x;   // region 0..13
    const int b  = blockIdx.y;   // batch
    const int c4 = threadIdx.x;

    const int iy = c_regY[r];
    const int ix = c_regX[r];
    const unsigned mask = c_imask[iy];

    const float4* __restrict__ M4 = (const float4*)g_M;
    float4 acc = make_float4(NEG_INF, NEG_INF, NEG_INF, NEG_INF);

#pragma unroll
    for (int s = 0; s < 7; ++s) {
        if (mask & (1u << s)) {
            float4 v = M4[((size_t)((b * 7 + s) * 6 + ix)) * 128 + c4];
            acc = fmax4(acc, v);
        }
    }

    ((float4*)out)[((size_t)(b * 14 + r)) * 128 + c4] = acc;
}

extern "C" void kernel_launch(void* const* d_in, const int* in_sizes, int n_in,
                              void* d_out, int out_size) {
    const float* x = (const float*)d_in[0];
    float* out = (float*)d_out;

    rmac_k1<<<dim3(7, 64), 128>>>(x);
    rmac_k2<<<dim3(14, 64), 128>>>(out);
}

// round 2
// speedup vs baseline: 1.4535x; 1.4535x over previous
#include <cuda_runtime.h>

// RMAC max-pooling, x: (64, 37, 37, 512) f32 NHWC -> out: (64, 14, 512) f32.
// 14 static regions = products of 6 axis-intervals over atomic segments with
// boundaries {0,9,13,18,19,24,27,37}.
//
// R2 change: K1 is now one block per (row, batch) -> 2368 perfectly uniform
// blocks (vs 448 imbalanced in R1, which ran at the pace of the len-10
// segment blocks). K1 writes per-row 6 x-interval maxes; K2 reduces over the
// region's y-range (L2-hot).

#define NEG_INF __int_as_float(0xff800000)

// Per-row x-interval maxes: [64][37][6][512] f32 = 29.1 MB scratch.
__device__ float g_M[64 * 37 * 6 * 512];

// region r -> (y-interval, x-interval); intervals:
//   0:[0,37) 1:[0,24) 2:[13,37) 3:[0,18) 4:[9,27) 5:[19,37)
__constant__ unsigned char c_regY[14] = {0, 1, 1, 2, 2, 3, 3, 3, 4, 4, 4, 5, 5, 5};
__constant__ unsigned char c_regX[14] = {0, 1, 2, 1, 2, 3, 4, 5, 3, 4, 5, 3, 4, 5};
__constant__ int c_y0[6] = {0, 0, 13, 0, 9, 19};
__constant__ int c_y1[6] = {37, 24, 37, 18, 27, 37};

__device__ __forceinline__ float4 fmax4(float4 a, float4 b) {
    return make_float4(fmaxf(a.x, b.x), fmaxf(a.y, b.y),
                       fmaxf(a.z, b.z), fmaxf(a.w, b.w));
}

// K1: one block per (h, b). 128 threads x float4 = 512 channels.
__global__ __launch_bounds__(128) void rmac_k1(const float* __restrict__ x) {
    const int h  = blockIdx.x;   // row 0..36
    const int b  = blockIdx.y;   // batch 0..63
    const int c4 = threadIdx.x;  // float4 channel group

    const float4* __restrict__ x4 = (const float4*)x;

    float4 ninf = make_float4(NEG_INF, NEG_INF, NEG_INF, NEG_INF);
    float4 a0 = ninf, a1 = ninf, a2 = ninf, a3 = ninf, a4 = ninf, a5 = ninf, a6 = ninf;

    // float4 base of this row: ((b*37 + h)*37 + w)*128 + c4
    size_t rb = ((size_t)(b * 37 + h) * 37) * 128 + c4;
#pragma unroll
    for (int w = 0; w < 37; ++w) {
        float4 v = x4[rb + (size_t)w * 128];
        if      (w <  9) a0 = fmax4(a0, v);
        else if (w < 13) a1 = fmax4(a1, v);
        else if (w < 18) a2 = fmax4(a2, v);
        else if (w < 19) a3 = fmax4(a3, v);
        else if (w < 24) a4 = fmax4(a4, v);
        else if (w < 27) a5 = fmax4(a5, v);
        else             a6 = fmax4(a6, v);
    }

    // Combine 7 w-segments -> 6 w-interval maxes.
    float4 I3 = fmax4(fmax4(a0, a1), a2);                        // [0,18)
    float4 I1 = fmax4(fmax4(I3, a3), a4);                        // [0,24)
    float4 I5 = fmax4(fmax4(a4, a5), a6);                        // [19,37)
    float4 I0 = fmax4(I1, fmax4(a5, a6));                        // [0,37)
    float4 I2 = fmax4(fmax4(a2, a3), I5);                        // [13,37)
    float4 I4 = fmax4(fmax4(a1, a2), fmax4(a3, fmax4(a4, a5)));  // [9,27)

    float4* M4 = (float4*)g_M;
    size_t ob = ((size_t)((b * 37 + h) * 6)) * 128 + c4;
    M4[ob + 0 * 128] = I0;
    M4[ob + 1 * 128] = I1;
    M4[ob + 2 * 128] = I2;
    M4[ob + 3 * 128] = I3;
    M4[ob + 4 * 128] = I4;
    M4[ob + 5 * 128] = I5;
}

// K2: one block per (region, batch); reduce over the region's y-range.
__global__ __launch_bounds__(128) void rmac_k2(float* __restrict__ out) {
    const int r  = blockIdx.x;   // region 0..13
    const int b  = blockIdx.y;   // batch
    const int c4 = threadIdx.x;

    const int iy = c_regY[r];
    const int ix = c_regX[r];
    const int y0 = c_y0[iy];
    const int y1 = c_y1[iy];

    const float4* __restrict__ M4 = (const float4*)g_M;
    float4 acc = make_float4(NEG_INF, NEG_INF, NEG_INF, NEG_INF);

#pragma unroll 4
    for (int h = y0; h < y1; ++h) {
        float4 v = M4[((size_t)((b * 37 + h) * 6 + ix)) * 128 + c4];
        acc = fmax4(acc, v);
    }

    ((float4*)out)[((size_t)(b * 14 + r)) * 128 + c4] = acc;
}

extern "C" void kernel_launch(void* const* d_in, const int* in_sizes, int n_in,
                              void* d_out, int out_size) {
    const float* x = (const float*)d_in[0];
    float* out = (float*)d_out;

    rmac_k1<<<dim3(37, 64), 128>>>(x);
    rmac_k2<<<dim3(14, 64), 128>>>(out);
}

// round 3
// speedup vs baseline: 1.5227x; 1.0476x over previous
#include <cuda_runtime.h>

// RMAC max-pooling, x: (64, 37, 37, 512) f32 NHWC -> out: (64, 14, 512) f32.
// 14 static regions = products of 6 x-intervals and 6 y-intervals:
//   x/y-int: 0:[0,37) 1:[0,24) 2:[13,37) 3:[0,18) 4:[9,27) 5:[19,37)
//   regions: r0:(y0,x0) r1:(y1,x1) r2:(y1,x2) r3:(y2,x1) r4:(y2,x2)
//            r5-7:(y3,x3..5) r8-10:(y4,x3..5) r11-13:(y5,x3..5)
//
// R3: fully fused streaming pass. K1 = 8 row-bands x 64 batch x 2 ch-halves
// (1024 uniform blocks, wave stretch 1.2%); each block folds its rows directly
// into 14 per-region register accumulators (row membership = cheap uniform
// predicates) and writes a small 14.7MB partial table. K2 maxes 8 partials.

#define NEG_INF __int_as_float(0xff800000)

#define NBANDS 8
// Partial region maxes: [64][8 bands][14 regions][512 ch] f32 = 14.7 MB.
__device__ float g_P[64 * NBANDS * 14 * 512];

__constant__ int c_b0[NBANDS] = {0, 5, 10, 15, 20, 25, 29, 33};
__constant__ int c_b1[NBANDS] = {5, 10, 15, 20, 25, 29, 33, 37};

__device__ __forceinline__ float2 fmax2(float2 a, float2 b) {
    return make_float2(fmaxf(a.x, b.x), fmaxf(a.y, b.y));
}
__device__ __forceinline__ float4 fmax4(float4 a, float4 b) {
    return make_float4(fmaxf(a.x, b.x), fmaxf(a.y, b.y),
                       fmaxf(a.z, b.z), fmaxf(a.w, b.w));
}

// K1: grid (8, 64, 2) x 128 threads, float2 per thread (256 ch per block).
__global__ __launch_bounds__(128) void rmac_k1(const float* __restrict__ x) {
    const int band = blockIdx.x;
    const int b    = blockIdx.y;
    const int half = blockIdx.z;
    const int c2   = half * 128 + threadIdx.x;   // float2 channel index 0..255

    const float2* __restrict__ x2 = (const float2*)x;

    const float2 ninf2 = make_float2(NEG_INF, NEG_INF);
    float2 acc[14];
#pragma unroll
    for (int r = 0; r < 14; ++r) acc[r] = ninf2;

    const int h0 = c_b0[band];
    const int h1 = c_b1[band];

    for (int h = h0; h < h1; ++h) {
        float2 s0 = ninf2, s1 = ninf2, s2 = ninf2, s3 = ninf2,
               s4 = ninf2, s5 = ninf2, s6 = ninf2;
        // float2 row base: ((b*37 + h)*37 + w)*256 + c2
        size_t rb = ((size_t)(b * 37 + h) * 37) * 256 + c2;
#pragma unroll
        for (int w = 0; w < 37; ++w) {
            float2 v = x2[rb + (size_t)w * 256];
            if      (w <  9) s0 = fmax2(s0, v);
            else if (w < 13) s1 = fmax2(s1, v);
            else if (w < 18) s2 = fmax2(s2, v);
            else if (w < 19) s3 = fmax2(s3, v);
            else if (w < 24) s4 = fmax2(s4, v);
            else if (w < 27) s5 = fmax2(s5, v);
            else             s6 = fmax2(s6, v);
        }

        // 7 w-segments -> 6 x-interval maxes.
        float2 I3 = fmax2(fmax2(s0, s1), s2);                        // [0,18)
        float2 I1 = fmax2(fmax2(I3, s3), s4);                        // [0,24)
        float2 I5 = fmax2(fmax2(s4, s5), s6);                        // [19,37)
        float2 I0 = fmax2(I1, fmax2(s5, s6));                        // [0,37)
        float2 I2 = fmax2(fmax2(s2, s3), I5);                        // [13,37)
        float2 I4 = fmax2(fmax2(s1, s2), fmax2(s3, fmax2(s4, s5)));  // [9,27)

        // Fold row into region accumulators (uniform predicates on h).
        acc[0] = fmax2(acc[0], I0);                                  // y[0,37)
        if (h < 24)            { acc[1] = fmax2(acc[1], I1);         // y[0,24)
                                 acc[2] = fmax2(acc[2], I2); }
        if (h >= 13)           { acc[3] = fmax2(acc[3], I1);         // y[13,37)
                                 acc[4] = fmax2(acc[4], I2); }
        if (h < 18)            { acc[5] = fmax2(acc[5], I3);         // y[0,18)
                                 acc[6] = fmax2(acc[6], I4);
                                 acc[7] = fmax2(acc[7], I5); }
        if (h >= 9 && h < 27)  { acc[8] = fmax2(acc[8], I3);         // y[9,27)
                                 acc[9] = fmax2(acc[9], I4);
                                 acc[10] = fmax2(acc[10], I5); }
        if (h >= 19)           { acc[11] = fmax2(acc[11], I3);       // y[19,37)
                                 acc[12] = fmax2(acc[12], I4);
                                 acc[13] = fmax2(acc[13], I5); }
    }

    // Write partials: g_P[b][band][r][512ch], float2 view.
    float2* P2 = (float2*)g_P;
    size_t ob = ((size_t)((b * NBANDS + band) * 14)) * 256 + c2;
#pragma unroll
    for (int r = 0; r < 14; ++r) {
        P2[ob + (size_t)r * 256] = acc[r];
    }
}

// K2: grid (14, 64) x 128 threads, float4; max over 8 band partials (L2-hot).
__global__ __launch_bounds__(128) void rmac_k2(float* __restrict__ out) {
    const int r  = blockIdx.x;
    const int b  = blockIdx.y;
    const int c4 = threadIdx.x;

    const float4* __restrict__ P4 = (const float4*)g_P;
    float4 a = make_float4(NEG_INF, NEG_INF, NEG_INF, NEG_INF);

#pragma unroll
    for (int band = 0; band < NBANDS; ++band) {
        float4 v = P4[((size_t)((b * NBANDS + band) * 14 + r)) * 128 + c4];
        a = fmax4(a, v);
    }

    ((float4*)out)[((size_t)(b * 14 + r)) * 128 + c4] = a;
}

extern "C" void kernel_launch(void* const* d_in, const int* in_sizes, int n_in,
                              void* d_out, int out_size) {
    const float* x = (const float*)d_in[0];
    float* out = (float*)d_out;

    rmac_k1<<<dim3(NBANDS, 64, 2), 128>>>(x);
    rmac_k2<<<dim3(14, 64), 128>>>(out);
}